// round 3
// baseline (speedup 1.0000x reference)
#include <cuda_runtime.h>
#include <cstdint>
#include <cstddef>

// ---------------------------------------------------------------------------
// Compile-time PGA(3,0,1) tables. Blade order matches the reference:
// idx : (), e0,e1,e2,e3, e01,e02,e03,e12,e13,e23, e012,e013,e023,e123, e0123
// ---------------------------------------------------------------------------
namespace ga {

__host__ __device__ constexpr unsigned bladeMask(int i) {
    constexpr unsigned m[16] = {0u,1u,2u,4u,8u, 3u,5u,9u,6u,10u,12u, 7u,11u,13u,14u, 15u};
    return m[i];
}
__host__ __device__ constexpr int idxOfMask(unsigned m) {
    constexpr int t[16] = {0,1,2,5,3,6,8,11,4,7,9,12,10,13,14,15};
    return t[m];
}
// #inversions when moving blade b (sorted) through blade a (sorted): left op a, right op b
__host__ __device__ constexpr int invCnt(unsigned a, unsigned b) {
    int s = 0;
    for (int i = 0; i < 4; ++i)
        if ((b >> i) & 1u)
            for (int j = i + 1; j < 4; ++j)
                if ((a >> j) & 1u) ++s;
    return s;
}
__host__ __device__ constexpr float gpSign(int j, int k) {
    unsigned a = bladeMask(j), b = bladeMask(k);
    if (a & b & 1u) return 0.0f;                       // e0*e0 = 0 (degenerate metric)
    return (invCnt(a, b) & 1) ? -1.0f : 1.0f;          // e1,e2,e3 square to +1
}
__host__ __device__ constexpr int gpTgt(int j, int k) {
    return idxOfMask(bladeMask(j) ^ bladeMask(k));
}
// dual sign: sign of blade(t) * complement(blade(t))  (disjoint -> parity only)
__host__ __device__ constexpr float dSign(int t) {
    unsigned m = bladeMask(t);
    return (invCnt(m, 15u ^ m) & 1) ? -1.0f : 1.0f;
}
// join coefficient for input blade indices (b, c): nonzero iff mask(b)|mask(c)==0xF,
// target blade = mask(b)&mask(c).
// jn[a,b,c] = dSign(idx(comp(a))) * outerSign(comp(b),comp(c)) * dSign(b) * dSign(c)
__host__ __device__ constexpr float jnCoef(int b, int c) {
    unsigned mb = bladeMask(b), mc = bladeMask(c);
    if ((mb | mc) != 15u) return 0.0f;
    unsigned ma = mb & mc;
    int ia = idxOfMask(15u ^ ma);
    unsigned cb = 15u ^ mb, cc = 15u ^ mc;
    float so = (invCnt(cb, cc) & 1) ? -1.0f : 1.0f;
    return dSign(ia) * so * dSign(b) * dSign(c);
}
__host__ __device__ constexpr int jnTgt(int b, int c) {
    return idxOfMask(bladeMask(b) & bladeMask(c));
}

template<int...> struct iseq {};
template<int N, int... S> struct mkseq : mkseq<N-1, N-1, S...> {};
template<int... S> struct mkseq<0, S...> { using type = iseq<S...>; };

template<int J, int K>
__device__ __forceinline__ void gpTerm(const float (&L)[16], const float (&R)[16], float (&h)[16]) {
    constexpr float s = gpSign(J, K);
    if constexpr (s > 0.5f) {
        constexpr int t = gpTgt(J, K);
        h[t] = fmaf(L[J], R[K], h[t]);
    } else if constexpr (s < -0.5f) {
        constexpr int t = gpTgt(J, K);
        h[t] = fmaf(-L[J], R[K], h[t]);
    }
}
template<int J, int... Ks>
__device__ __forceinline__ void gpRow(const float (&L)[16], const float (&R)[16], float (&h)[16], iseq<Ks...>) {
    (gpTerm<J, Ks>(L, R, h), ...);
}
template<int... Js>
__device__ __forceinline__ void gpAll(const float (&L)[16], const float (&R)[16], float (&h)[16], iseq<Js...>) {
    (gpRow<Js>(L, R, h, typename mkseq<16>::type{}), ...);
}

template<int J, int K>
__device__ __forceinline__ void jnTerm(const float (&L)[16], const float (&R)[16], float (&h)[16]) {
    constexpr float s = jnCoef(J, K);
    if constexpr (s > 0.5f) {
        constexpr int t = jnTgt(J, K);
        h[t] = fmaf(L[J], R[K], h[t]);
    } else if constexpr (s < -0.5f) {
        constexpr int t = jnTgt(J, K);
        h[t] = fmaf(-L[J], R[K], h[t]);
    }
}
template<int J, int... Ks>
__device__ __forceinline__ void jnRow(const float (&L)[16], const float (&R)[16], float (&h)[16], iseq<Ks...>) {
    (jnTerm<J, Ks>(L, R, h), ...);
}
template<int... Js>
__device__ __forceinline__ void jnAll(const float (&L)[16], const float (&R)[16], float (&h)[16], iseq<Js...>) {
    (jnRow<Js>(L, R, h, typename mkseq<16>::type{}), ...);
}

// Equivariant-linear accumulation for one input channel: o += W(basis-structure) * x
// Grade diag: grades = [0,1,1,1,1, 2,2,2,2,2,2, 3,3,3,3, 4]
// e0 wedge (all +1): j=1<-k=0 (b=5); j=5,6,7<-k=2,3,4 (b=6); j=11,12,13<-k=8,9,10 (b=7); j=15<-k=14 (b=8)
__device__ __forceinline__ void linAcc(float (&o)[16], const float (&w)[9], const float (&x)[16]) {
    o[0]  = fmaf(w[0], x[0],  o[0]);
    o[1]  = fmaf(w[1], x[1],  o[1]);  o[1]  = fmaf(w[5], x[0],  o[1]);
    o[2]  = fmaf(w[1], x[2],  o[2]);
    o[3]  = fmaf(w[1], x[3],  o[3]);
    o[4]  = fmaf(w[1], x[4],  o[4]);
    o[5]  = fmaf(w[2], x[5],  o[5]);  o[5]  = fmaf(w[6], x[2],  o[5]);
    o[6]  = fmaf(w[2], x[6],  o[6]);  o[6]  = fmaf(w[6], x[3],  o[6]);
    o[7]  = fmaf(w[2], x[7],  o[7]);  o[7]  = fmaf(w[6], x[4],  o[7]);
    o[8]  = fmaf(w[2], x[8],  o[8]);
    o[9]  = fmaf(w[2], x[9],  o[9]);
    o[10] = fmaf(w[2], x[10], o[10]);
    o[11] = fmaf(w[3], x[11], o[11]); o[11] = fmaf(w[7], x[8],  o[11]);
    o[12] = fmaf(w[3], x[12], o[12]); o[12] = fmaf(w[7], x[9],  o[12]);
    o[13] = fmaf(w[3], x[13], o[13]); o[13] = fmaf(w[7], x[10], o[13]);
    o[14] = fmaf(w[3], x[14], o[14]);
    o[15] = fmaf(w[4], x[15], o[15]); o[15] = fmaf(w[8], x[14], o[15]);
}

} // namespace ga

// ---------------------------------------------------------------------------
// Kernel
// ---------------------------------------------------------------------------
#define NW 12
#define NTHREADS (NW * 32)

// shared memory float offsets
#define OFF_WA    0        // [32 i][9 b][32 lane]  laneA weights (left / jl)
#define OFF_WB    9216     // [32 i][9 b][32 lane]  laneB weights (right / jr)
#define OFF_WO    18432    // [32 c][9 b][32 o]     output mv weights
#define OFF_SA    27648    // [64 s][32 lane]
#define OFF_SB    29696    // [64 s][32 lane]
#define OFF_S2MV  31744    // [64 s][32 o]
#define OFF_WM1   33792    // [32 c][32 o]   out_s rows 0..31
#define OFF_WM2   34816    // [32 c][32 o]   out_s rows 32..63
#define OFF_WS1   35840    // [64 s][32 o]
#define OFF_WS2   37888    // [64 s][32 o]
#define OFF_STG   39936    // per-warp staging: 512 x + 64 sc + 32*20 hidden = 1216
#define STG_PER_WARP 1216
#define SMEM_FLOATS (OFF_STG + NW * STG_PER_WARP)
#define SMEM_BYTES  (SMEM_FLOATS * 4)

__global__ void __launch_bounds__(NTHREADS, 1)
gb_kernel(const float* __restrict__ mv,      // [ntok][32][16]
          const float* __restrict__ refmv,   // [ntok][16]
          const float* __restrict__ scal,    // [ntok][64]
          const float* __restrict__ wLmv, const float* __restrict__ wLs,
          const float* __restrict__ wRmv, const float* __restrict__ wRs,
          const float* __restrict__ wJLmv, const float* __restrict__ wJLs,
          const float* __restrict__ wJRmv, const float* __restrict__ wJRs,
          const float* __restrict__ wOmv,    // [32 o][32 c][9 b]
          const float* __restrict__ wS2mv,   // [32 o][64 s]
          const float* __restrict__ wMvs2s,  // [64 o][32 c]
          const float* __restrict__ wS2s,    // [64 o][64 s]
          float* __restrict__ out,           // [ntok][32][16]
          float* __restrict__ outS,          // [ntok][64]
          int ntok)
{
    extern __shared__ float sm[];
    float* WA   = sm + OFF_WA;
    float* WB   = sm + OFF_WB;
    float* WO   = sm + OFF_WO;
    float* SA   = sm + OFF_SA;
    float* SB   = sm + OFF_SB;
    float* S2MV = sm + OFF_S2MV;
    float* WM1  = sm + OFF_WM1;
    float* WM2  = sm + OFF_WM2;
    float* WS1  = sm + OFF_WS1;
    float* WS2  = sm + OFF_WS2;

    const int tid  = threadIdx.x;
    const int lane = tid & 31;
    const int wid  = tid >> 5;

    // ---- stage all weights to smem, lane-permuted ----
    // Lane mapping for the 4 input linears:
    //   lane<16  : A=left[lane],  B=right[lane]
    //   lane>=16 : A=jl[lane-16], B=jr[lane-16]
    for (int idx = tid; idx < 9216; idx += NTHREADS) {
        const int l   = idx & 31;
        const int off = idx >> 5;               // i*9+b  (or c*9+b for WO)
        WA[idx] = (l < 16) ? wLmv[l * 288 + off] : wJLmv[(l - 16) * 288 + off];
        WB[idx] = (l < 16) ? wRmv[l * 288 + off] : wJRmv[(l - 16) * 288 + off];
        WO[idx] = wOmv[l * 288 + off];          // l = o
    }
    for (int idx = tid; idx < 2048; idx += NTHREADS) {
        const int l = idx & 31;
        const int s = idx >> 5;
        SA[idx]   = (l < 16) ? wLs[l * 64 + s] : wJLs[(l - 16) * 64 + s];
        SB[idx]   = (l < 16) ? wRs[l * 64 + s] : wJRs[(l - 16) * 64 + s];
        S2MV[idx] = wS2mv[l * 64 + s];
        WS1[idx]  = wS2s[l * 64 + s];
        WS2[idx]  = wS2s[(32 + l) * 64 + s];
    }
    for (int idx = tid; idx < 1024; idx += NTHREADS) {
        const int l = idx & 31;
        const int c = idx >> 5;
        WM1[idx] = wMvs2s[l * 32 + c];
        WM2[idx] = wMvs2s[(32 + l) * 32 + c];
    }
    __syncthreads();

    float* xs = sm + OFF_STG + wid * STG_PER_WARP; // 512 floats [32 i][16 j]
    float* sc = xs + 512;                          // 64 floats
    float* hs = sc + 64;                           // [32 c][20] padded hidden

    const int gw = blockIdx.x * NW + wid;
    const int nw = gridDim.x * NW;

    for (int tok = gw; tok < ntok; tok += nw) {
        // ---- stage token inputs ----
        const float4* gx = reinterpret_cast<const float4*>(mv) + (size_t)tok * 128;
        float4* xs4 = reinterpret_cast<float4*>(xs);
        #pragma unroll
        for (int it = 0; it < 4; ++it) xs4[it * 32 + lane] = gx[it * 32 + lane];
        sc[lane]      = scal[(size_t)tok * 64 + lane];
        sc[lane + 32] = scal[(size_t)tok * 64 + 32 + lane];
        const float ref15 = refmv[(size_t)tok * 16 + 15];
        __syncwarp();

        // ---- the two input equi-linears owned by this lane ----
        float A[16], Bv[16];
        #pragma unroll
        for (int j = 0; j < 16; ++j) { A[j] = 0.0f; Bv[j] = 0.0f; }

        #pragma unroll 8
        for (int s = 0; s < 64; ++s) {
            const float sv = sc[s];
            A[0]  = fmaf(SA[s * 32 + lane], sv, A[0]);
            Bv[0] = fmaf(SB[s * 32 + lane], sv, Bv[0]);
        }

        #pragma unroll 4
        for (int i = 0; i < 32; ++i) {
            float xr[16];
            {
                const float4 x0 = *reinterpret_cast<const float4*>(xs + i * 16 + 0);
                const float4 x1 = *reinterpret_cast<const float4*>(xs + i * 16 + 4);
                const float4 x2 = *reinterpret_cast<const float4*>(xs + i * 16 + 8);
                const float4 x3 = *reinterpret_cast<const float4*>(xs + i * 16 + 12);
                xr[0]=x0.x; xr[1]=x0.y; xr[2]=x0.z; xr[3]=x0.w;
                xr[4]=x1.x; xr[5]=x1.y; xr[6]=x1.z; xr[7]=x1.w;
                xr[8]=x2.x; xr[9]=x2.y; xr[10]=x2.z; xr[11]=x2.w;
                xr[12]=x3.x; xr[13]=x3.y; xr[14]=x3.z; xr[15]=x3.w;
            }
            float wa[9], wb[9];
            #pragma unroll
            for (int b = 0; b < 9; ++b) {
                wa[b] = WA[(i * 9 + b) * 32 + lane];
                wb[b] = WB[(i * 9 + b) * 32 + lane];
            }
            ga::linAcc(A, wa, xr);
            ga::linAcc(Bv, wb, xr);
        }

        // ---- bilinear: gp on lanes 0..15, join on lanes 16..31 ----
        float h[16];
        #pragma unroll
        for (int j = 0; j < 16; ++j) h[j] = 0.0f;
        if (lane < 16) {
            ga::gpAll(A, Bv, h, typename ga::mkseq<16>::type{});
        } else {
            ga::jnAll(A, Bv, h, typename ga::mkseq<16>::type{});
            #pragma unroll
            for (int j = 0; j < 16; ++j) h[j] *= ref15;
        }
        #pragma unroll
        for (int m = 0; m < 4; ++m)
            *reinterpret_cast<float4*>(hs + lane * 20 + m * 4) =
                make_float4(h[m*4+0], h[m*4+1], h[m*4+2], h[m*4+3]);
        __syncwarp();

        // ---- output equi-linear: lane = output channel o (32) ----
        float O[16];
        #pragma unroll
        for (int j = 0; j < 16; ++j) O[j] = 0.0f;

        #pragma unroll 4
        for (int c = 0; c < 32; ++c) {
            float hr[16];
            {
                const float4 h0 = *reinterpret_cast<const float4*>(hs + c * 20 + 0);
                const float4 h1 = *reinterpret_cast<const float4*>(hs + c * 20 + 4);
                const float4 h2 = *reinterpret_cast<const float4*>(hs + c * 20 + 8);
                const float4 h3 = *reinterpret_cast<const float4*>(hs + c * 20 + 12);
                hr[0]=h0.x; hr[1]=h0.y; hr[2]=h0.z; hr[3]=h0.w;
                hr[4]=h1.x; hr[5]=h1.y; hr[6]=h1.z; hr[7]=h1.w;
                hr[8]=h2.x; hr[9]=h2.y; hr[10]=h2.z; hr[11]=h2.w;
                hr[12]=h3.x; hr[13]=h3.y; hr[14]=h3.z; hr[15]=h3.w;
            }
            float wo[9];
            #pragma unroll
            for (int b = 0; b < 9; ++b) wo[b] = WO[(c * 9 + b) * 32 + lane];
            ga::linAcc(O, wo, hr);
        }
        #pragma unroll 8
        for (int s = 0; s < 64; ++s)
            O[0] = fmaf(S2MV[s * 32 + lane], sc[s], O[0]);

        float* om = out + (size_t)tok * 512 + lane * 16;
        #pragma unroll
        for (int m = 0; m < 4; ++m)
            *reinterpret_cast<float4*>(om + m * 4) =
                make_float4(O[m*4+0], O[m*4+1], O[m*4+2], O[m*4+3]);

        // ---- scalar outputs: lane handles rows o and o+32 ----
        float os1 = 0.0f, os2 = 0.0f;
        #pragma unroll 4
        for (int c = 0; c < 32; ++c) {
            const float hv = hs[c * 20];
            os1 = fmaf(WM1[c * 32 + lane], hv, os1);
            os2 = fmaf(WM2[c * 32 + lane], hv, os2);
        }
        #pragma unroll 8
        for (int s = 0; s < 64; ++s) {
            const float sv = sc[s];
            os1 = fmaf(WS1[s * 32 + lane], sv, os1);
            os2 = fmaf(WS2[s * 32 + lane], sv, os2);
        }
        outS[(size_t)tok * 64 + lane]      = os1;
        outS[(size_t)tok * 64 + 32 + lane] = os2;
        __syncwarp();   // staging reused next iteration
    }
}

// ---------------------------------------------------------------------------
// Launch
// ---------------------------------------------------------------------------
extern "C" void kernel_launch(void* const* d_in, const int* in_sizes, int n_in,
                              void* d_out, int out_size) {
    const float* mv     = (const float*)d_in[0];
    const float* refmv  = (const float*)d_in[1];
    const float* scal   = (const float*)d_in[2];
    // d_in[3..5] = basis, gp, jn (structure hardcoded at compile time)
    const float* wLmv   = (const float*)d_in[6];
    const float* wLs    = (const float*)d_in[7];
    const float* wRmv   = (const float*)d_in[8];
    const float* wRs    = (const float*)d_in[9];
    const float* wJLmv  = (const float*)d_in[10];
    const float* wJLs   = (const float*)d_in[11];
    const float* wJRmv  = (const float*)d_in[12];
    const float* wJRs   = (const float*)d_in[13];
    const float* wOmv   = (const float*)d_in[14];
    const float* wS2mv  = (const float*)d_in[15];
    const float* wMvs2s = (const float*)d_in[16];
    const float* wS2s   = (const float*)d_in[17];

    const int ntok = in_sizes[0] / 512;          // 32768
    float* out  = (float*)d_out;                 // [ntok*512] out_mv
    float* outS = out + (size_t)ntok * 512;      // [ntok*64]  out_s

    int dev = 0;
    cudaGetDevice(&dev);
    int nsm = 148;
    cudaDeviceGetAttribute(&nsm, cudaDevAttrMultiProcessorCount, dev);

    cudaFuncSetAttribute(gb_kernel, cudaFuncAttributeMaxDynamicSharedMemorySize, SMEM_BYTES);

    gb_kernel<<<nsm, NTHREADS, SMEM_BYTES>>>(
        mv, refmv, scal,
        wLmv, wLs, wRmv, wRs, wJLmv, wJLs, wJRmv, wJRs,
        wOmv, wS2mv, wMvs2s, wS2s,
        out, outS, ntok);
}